// round 11
// baseline (speedup 1.0000x reference)
#include <cuda_runtime.h>
#include <cuda_bf16.h>

// Problem constants
#define SQ   1024   // sequence length
#define BB   8      // batch
#define HH   1024   // hidden
#define NHD  16     // num heads
#define HDI  64     // head dim

// ---------------------------------------------------------------------------
// Scratch (device globals: no allocation allowed)
// ---------------------------------------------------------------------------
__device__ float g_qp[(size_t)BB * NHD * SQ * HDI];   // [b][h][s][d]
__device__ float g_kp[(size_t)BB * NHD * SQ * HDI];
__device__ float g_vp[(size_t)BB * NHD * SQ * HDI];
__device__ float g_bias[BB * SQ];                     // -1e6 * mask
__device__ int   g_mmode;

// ---------------------------------------------------------------------------
// TF32 helpers
// ---------------------------------------------------------------------------
__device__ __forceinline__ unsigned f2tf(float x) {
    unsigned u;
    asm("cvt.rna.tf32.f32 %0, %1;" : "=r"(u) : "f"(x));
    return u;
}
__device__ __forceinline__ uint4 f2tf4(float4 v) {
    return make_uint4(f2tf(v.x), f2tf(v.y), f2tf(v.z), f2tf(v.w));
}
__device__ __forceinline__ void mma8(float c[4], const unsigned a[4], const unsigned b[2]) {
    asm volatile(
        "mma.sync.aligned.m16n8k8.row.col.f32.tf32.tf32.f32 "
        "{%0,%1,%2,%3}, {%4,%5,%6,%7}, {%8,%9}, {%0,%1,%2,%3};"
        : "+f"(c[0]), "+f"(c[1]), "+f"(c[2]), "+f"(c[3])
        : "r"(a[0]), "r"(a[1]), "r"(a[2]), "r"(a[3]),
          "r"(b[0]), "r"(b[1]));
}

// ---------------------------------------------------------------------------
// Mask dtype detection + bias build
// ---------------------------------------------------------------------------
__global__ void k_detect(const unsigned* __restrict__ m) {
    bool i32 = true, f32 = true;
    for (int i = 0; i < 2048; i++) {
        unsigned v = m[i];
        if (v > 1u) i32 = false;
        if (v != 0u && v != 0x3F800000u) f32 = false;
    }
    g_mmode = i32 ? 1 : (f32 ? 2 : 0);
}
__global__ void k_bias(const void* __restrict__ mask) {
    int i = blockIdx.x * blockDim.x + threadIdx.x;
    if (i >= BB * SQ) return;
    int mode = g_mmode;
    float v;
    if (mode == 1)      v = (float)((const int*)mask)[i];
    else if (mode == 2) v = ((const float*)mask)[i];
    else                v = (float)((const unsigned char*)mask)[i];
    g_bias[i] = v * -1000000.0f;
}

// ---------------------------------------------------------------------------
// Projection GEMM, register-double-buffered (prefetch next k-tile into regs
// while MMAs run on the current smem tile).  All 3 GEMMs via blockIdx.z.
// BM=128, BN=128, BK=32, 256 thr = 8 warps (2 x 4), warp tile 64x32.
// ---------------------------------------------------------------------------
__global__ __launch_bounds__(256) void k_proj(
    const float* __restrict__ Xq, const float* __restrict__ Xk, const float* __restrict__ Xv,
    const float* __restrict__ Wq, const float* __restrict__ bq,
    const float* __restrict__ Wk, const float* __restrict__ bk,
    const float* __restrict__ Wv, const float* __restrict__ bv)
{
    const int which = blockIdx.z;
    const float* X    = (which == 0) ? Xq : ((which == 1) ? Xk : Xv);
    const float* W    = (which == 0) ? Wq : ((which == 1) ? Wk : Wv);
    const float* bias = (which == 0) ? bq : ((which == 1) ? bk : bv);
    float* Out        = (which == 0) ? g_qp : ((which == 1) ? g_kp : g_vp);

    __shared__ unsigned As[128][36];
    __shared__ unsigned Bs[128][36];

    const int tid  = threadIdx.x;
    const int lane = tid & 31;
    const int warp = tid >> 5;
    const int wm   = warp >> 2;     // 0..1
    const int wn   = warp & 3;      // 0..3
    const int g    = lane >> 2;
    const int t4   = lane & 3;
    const int bm   = blockIdx.y * 128;
    const int bn   = blockIdx.x * 128;
    const int fr   = tid >> 3;            // fill row
    const int fc   = (tid & 7) << 2;      // fill col

    float acc[4][4][4];
#pragma unroll
    for (int mt = 0; mt < 4; mt++)
#pragma unroll
        for (int nt = 0; nt < 4; nt++)
#pragma unroll
            for (int i = 0; i < 4; i++) acc[mt][nt][i] = 0.0f;

    // prefetch k-tile 0 into registers
    float4 ra[4], rb[4];
#pragma unroll
    for (int t = 0; t < 4; t++) {
        ra[t] = *reinterpret_cast<const float4*>(&X[(size_t)(bm + fr + t * 32) * HH + fc]);
        rb[t] = *reinterpret_cast<const float4*>(&W[(size_t)(bn + fr + t * 32) * HH + fc]);
    }

    for (int k0 = 0; k0 < HH; k0 += 32) {
        // commit prefetched tile to smem (tf32)
#pragma unroll
        for (int t = 0; t < 4; t++) {
            *reinterpret_cast<uint4*>(&As[fr + t * 32][fc]) = f2tf4(ra[t]);
            *reinterpret_cast<uint4*>(&Bs[fr + t * 32][fc]) = f2tf4(rb[t]);
        }
        __syncthreads();

        // issue next tile's LDGs — latency hidden behind the MMAs below
        if (k0 + 32 < HH) {
#pragma unroll
            for (int t = 0; t < 4; t++) {
                ra[t] = *reinterpret_cast<const float4*>(
                    &X[(size_t)(bm + fr + t * 32) * HH + k0 + 32 + fc]);
                rb[t] = *reinterpret_cast<const float4*>(
                    &W[(size_t)(bn + fr + t * 32) * HH + k0 + 32 + fc]);
            }
        }

#pragma unroll
        for (int k8 = 0; k8 < 4; k8++) {
            const int kk = k8 * 8;
            unsigned a[4][4], bf[4][2];
#pragma unroll
            for (int mt = 0; mt < 4; mt++) {
                const int r = wm * 64 + mt * 16;
                a[mt][0] = As[r + g][kk + t4];
                a[mt][1] = As[r + g + 8][kk + t4];
                a[mt][2] = As[r + g][kk + t4 + 4];
                a[mt][3] = As[r + g + 8][kk + t4 + 4];
            }
#pragma unroll
            for (int nt = 0; nt < 4; nt++) {
                const int n = wn * 32 + nt * 8 + g;
                bf[nt][0] = Bs[n][kk + t4];
                bf[nt][1] = Bs[n][kk + t4 + 4];
            }
#pragma unroll
            for (int mt = 0; mt < 4; mt++)
#pragma unroll
                for (int nt = 0; nt < 4; nt++)
                    mma8(acc[mt][nt], a[mt], bf[nt]);
        }
        __syncthreads();
    }

    // Epilogue: add bias, scatter to [b][h][s][d]
#pragma unroll
    for (int mt = 0; mt < 4; mt++) {
        const int r0 = bm + wm * 64 + mt * 16 + g;
#pragma unroll
        for (int nt = 0; nt < 4; nt++) {
            const int n0  = bn + wn * 32 + nt * 8 + t4 * 2;
            const float b0v = bias[n0];
            const float b1v = bias[n0 + 1];
            const int h = n0 >> 6;
            const int d = n0 & 63;
#pragma unroll
            for (int half = 0; half < 2; half++) {
                const int m  = r0 + half * 8;
                const int s  = m >> 3;     // m = s*B + b
                const int bb = m & 7;
                float2 val = make_float2(acc[mt][nt][half * 2 + 0] + b0v,
                                         acc[mt][nt][half * 2 + 1] + b1v);
                *reinterpret_cast<float2*>(
                    &Out[(((size_t)bb * NHD + h) * SQ + s) * HDI + d]) = val;
            }
        }
    }
}

// ---------------------------------------------------------------------------
// Fused two-pass flash attention with paired-column permuted smem layout.
// Within each 8-column k-octet, column k is stored at slot 2*(k&3) + (k>>2):
// order [0,4,1,5,2,6,3,7].  The mma fragment pair (t4, t4+4) is then one
// 8-byte LDS.64 at offset 2*t4.  All tile row strides = 72 (== 8 mod 32 ->
// conflict-free LDS.64 per half-warp).
// bias lives in Qs spare cols 64..71; row sums/inv in Ps spare cols 64..66.
// smem = 72*(128+64+64+128)*4 = 108KB -> 2 blocks/SM.
// ---------------------------------------------------------------------------
#define ST 72
#define F_QS (128 * ST)
#define F_KS (64 * ST)
#define F_VS (64 * ST)
#define F_PS (128 * ST)
#define F_SMEM_BYTES ((F_QS + F_KS + F_VS + F_PS) * 4)

__global__ __launch_bounds__(256, 2) void k_attn(float* __restrict__ attn,
                                                 float* __restrict__ ctx)
{
    extern __shared__ unsigned usm[];
    unsigned* Qs = usm;
    unsigned* Ks = Qs + F_QS;
    unsigned* Vs = Ks + F_KS;
    unsigned* Ps = Vs + F_VS;
    float*    QsF = (float*)Qs;    // bias in cols 64..71
    float*    PsF = (float*)Ps;    // sums in cols 64..65, inv in col 66

    const int tid  = threadIdx.x;
    const int lane = tid & 31;
    const int warp = tid >> 5;
    const int g    = lane >> 2;
    const int t4   = lane & 3;
    const int wm   = warp >> 1;    // 0..3
    const int wn   = warp & 1;     // 0..1
    const int qb   = blockIdx.x;
    const int bh   = blockIdx.y;
    const int b    = bh >> 4;
    const int h    = bh & 15;
    const int pp0  = ((t4 & 1) << 2) | (t4 >> 1);   // pslot(2*t4)
    const int fr   = tid >> 4;            // fill row (64-row tiles)
    const int fc   = (tid & 15) << 2;     // fill col 0..60
    const int fcb  = (fc & 56) + ((fc & 4) ? 1 : 0);  // permuted slot base

    const float* Qg = g_qp + ((size_t)bh * SQ + qb * 128) * HDI;
    const float* Kg = g_kp + (size_t)bh * SQ * HDI;
    const float* Vg = g_vp + (size_t)bh * SQ * HDI;

    // Load Q tile (128x64 tf32, permuted octets) + bias into Qs spare cols
#pragma unroll
    for (int t = 0; t < 8; t++) {
        int i4 = tid + t * 256;
        int r  = i4 >> 4;
        int c  = (i4 & 15) << 2;
        uint4 tv = f2tf4(*reinterpret_cast<const float4*>(&Qg[r * 64 + c]));
        unsigned* p = &Qs[r * ST + (c & 56) + ((c & 4) ? 1 : 0)];
        p[0] = tv.x; p[2] = tv.y; p[4] = tv.z; p[6] = tv.w;
    }
#pragma unroll
    for (int t = 0; t < 4; t++) {
        int i = tid + t * 256;
        QsF[(i & 127) * ST + 64 + (i >> 7)] = g_bias[b * SQ + i];
    }

    // ======================= Pass 1: row sums ============================
    float rs[2][2] = {};
    for (int kt = 0; kt < 16; kt++) {
        __syncthreads();   // protect Ks reuse (and Qs/bias fill on kt=0)
#pragma unroll
        for (int t = 0; t < 4; t++) {
            int r = fr + t * 16;
            uint4 tv = f2tf4(*reinterpret_cast<const float4*>(
                &Kg[(size_t)(kt * 64 + r) * 64 + fc]));
            unsigned* p = &Ks[r * ST + fcb];
            p[0] = tv.x; p[2] = tv.y; p[4] = tv.z; p[6] = tv.w;
        }
        __syncthreads();

        float acc[2][4][4] = {};
#pragma unroll
        for (int k8 = 0; k8 < 8; k8++) {
            const int kk = k8 * 8 + 2 * t4;
            unsigned a[2][4], bf[4][2];
#pragma unroll
            for (int mt = 0; mt < 2; mt++) {
                const int r = wm * 32 + mt * 16;
                uint2 lo = *reinterpret_cast<const uint2*>(&Qs[(r + g) * ST + kk]);
                uint2 hi = *reinterpret_cast<const uint2*>(&Qs[(r + g + 8) * ST + kk]);
                a[mt][0] = lo.x; a[mt][1] = hi.x; a[mt][2] = lo.y; a[mt][3] = hi.y;
            }
#pragma unroll
            for (int nt = 0; nt < 4; nt++) {
                const int n = wn * 32 + nt * 8 + g;
                uint2 bb = *reinterpret_cast<const uint2*>(&Ks[n * ST + kk]);
                bf[nt][0] = bb.x; bf[nt][1] = bb.y;
            }
#pragma unroll
            for (int mt = 0; mt < 2; mt++)
#pragma unroll
                for (int nt = 0; nt < 4; nt++)
                    mma8(acc[mt][nt], a[mt], bf[nt]);
        }
#pragma unroll
        for (int mt = 0; mt < 2; mt++)
#pragma unroll
            for (int half = 0; half < 2; half++)
#pragma unroll
                for (int nt = 0; nt < 4; nt++) {
                    const int cl = kt * 64 + wn * 32 + nt * 8 + t4 * 2;
                    const float bi0 = QsF[(cl & 127) * ST + 64 + (cl >> 7)];
                    const float bi1 = QsF[((cl + 1) & 127) * ST + 64 + ((cl + 1) >> 7)];
                    rs[mt][half] += __expf(acc[mt][nt][half * 2 + 0] * 0.125f + bi0)
                                  + __expf(acc[mt][nt][half * 2 + 1] * 0.125f + bi1);
                }
    }
    // reduce over t4 lanes, combine both wn warps via Ps spare cols
#pragma unroll
    for (int mt = 0; mt < 2; mt++)
#pragma unroll
        for (int half = 0; half < 2; half++) {
            float v = rs[mt][half];
            v += __shfl_xor_sync(0xffffffffu, v, 1);
            v += __shfl_xor_sync(0xffffffffu, v, 2);
            if (t4 == 0) {
                const int row = wm * 32 + mt * 16 + g + half * 8;
                PsF[row * ST + 64 + wn] = v;
            }
        }
    __syncthreads();
    if (tid < 128) PsF[tid * ST + 66] = 1.0f / (PsF[tid * ST + 64] + PsF[tid * ST + 65]);

    // ======================= Pass 2: attn + O ============================
    float o[2][4][4] = {};
    float* attn_base = attn + ((size_t)bh * SQ + qb * 128) * SQ;

    for (int kt = 0; kt < 16; kt++) {
        __syncthreads();   // prev PV reads done; inv visible on kt=0
#pragma unroll
        for (int t = 0; t < 4; t++) {
            int r = fr + t * 16;
            uint4 tv = f2tf4(*reinterpret_cast<const float4*>(
                &Kg[(size_t)(kt * 64 + r) * 64 + fc]));
            unsigned* p = &Ks[r * ST + fcb];
            p[0] = tv.x; p[2] = tv.y; p[4] = tv.z; p[6] = tv.w;
            // V tile plain layout (scalar B-frag loads are conflict-free)
            *reinterpret_cast<uint4*>(&Vs[r * ST + fc]) = f2tf4(
                *reinterpret_cast<const float4*>(&Vg[(size_t)(kt * 64 + r) * 64 + fc]));
        }
        __syncthreads();

        float acc[2][4][4] = {};
#pragma unroll
        for (int k8 = 0; k8 < 8; k8++) {
            const int kk = k8 * 8 + 2 * t4;
            unsigned a[2][4], bf[4][2];
#pragma unroll
            for (int mt = 0; mt < 2; mt++) {
                const int r = wm * 32 + mt * 16;
                uint2 lo = *reinterpret_cast<const uint2*>(&Qs[(r + g) * ST + kk]);
                uint2 hi = *reinterpret_cast<const uint2*>(&Qs[(r + g + 8) * ST + kk]);
                a[mt][0] = lo.x; a[mt][1] = hi.x; a[mt][2] = lo.y; a[mt][3] = hi.y;
            }
#pragma unroll
            for (int nt = 0; nt < 4; nt++) {
                const int n = wn * 32 + nt * 8 + g;
                uint2 bb = *reinterpret_cast<const uint2*>(&Ks[n * ST + kk]);
                bf[nt][0] = bb.x; bf[nt][1] = bb.y;
            }
#pragma unroll
            for (int mt = 0; mt < 2; mt++)
#pragma unroll
                for (int nt = 0; nt < 4; nt++)
                    mma8(acc[mt][nt], a[mt], bf[nt]);
        }

        // normalized exp -> attn (single streaming write) + Ps (permuted tf32)
#pragma unroll
        for (int mt = 0; mt < 2; mt++)
#pragma unroll
            for (int half = 0; half < 2; half++) {
                const int row = wm * 32 + mt * 16 + g + half * 8;
                const float inv = PsF[row * ST + 66];
#pragma unroll
                for (int nt = 0; nt < 4; nt++) {
                    const int cl  = wn * 32 + nt * 8 + t4 * 2;
                    const int key = kt * 64 + cl;
                    const float bi0 = QsF[(key & 127) * ST + 64 + (key >> 7)];
                    const float bi1 = QsF[((key + 1) & 127) * ST + 64 + ((key + 1) >> 7)];
                    float p0 = __expf(acc[mt][nt][half * 2 + 0] * 0.125f + bi0) * inv;
                    float p1 = __expf(acc[mt][nt][half * 2 + 1] * 0.125f + bi1) * inv;
                    __stcs(reinterpret_cast<float2*>(&attn_base[(size_t)row * SQ + key]),
                           make_float2(p0, p1));
                    unsigned* pb = &Ps[row * ST + (cl & 56)];
                    pb[pp0]     = f2tf(p0);
                    pb[pp0 + 2] = f2tf(p1);
                }
            }
        __syncthreads();   // Ps complete

        // O += P . V
#pragma unroll
        for (int k8 = 0; k8 < 8; k8++) {
            const int kk = k8 * 8;
            unsigned a[2][4], bf[4][2];
#pragma unroll
            for (int mt = 0; mt < 2; mt++) {
                const int r = wm * 32 + mt * 16;
                uint2 lo = *reinterpret_cast<const uint2*>(&Ps[(r + g) * ST + kk + 2 * t4]);
                uint2 hi = *reinterpret_cast<const uint2*>(&Ps[(r + g + 8) * ST + kk + 2 * t4]);
                a[mt][0] = lo.x; a[mt][1] = hi.x; a[mt][2] = lo.y; a[mt][3] = hi.y;
            }
#pragma unroll
            for (int nt = 0; nt < 4; nt++) {
                const int n = wn * 32 + nt * 8 + g;   // head-dim column
                bf[nt][0] = Vs[(kk + t4) * ST + n];
                bf[nt][1] = Vs[(kk + t4 + 4) * ST + n];
            }
#pragma unroll
            for (int mt = 0; mt < 2; mt++)
#pragma unroll
                for (int nt = 0; nt < 4; nt++)
                    mma8(o[mt][nt], a[mt], bf[nt]);
        }
    }

    // Epilogue: ctx[s][b][h*64+d]  (already normalized)
#pragma unroll
    for (int mt = 0; mt < 2; mt++)
#pragma unroll
        for (int nt = 0; nt < 4; nt++)
#pragma unroll
            for (int half = 0; half < 2; half++) {
                int row = wm * 32 + mt * 16 + g + half * 8;
                int s   = qb * 128 + row;
                int d   = wn * 32 + nt * 8 + t4 * 2;
                float2 val = make_float2(o[mt][nt][half * 2 + 0],
                                         o[mt][nt][half * 2 + 1]);
                *reinterpret_cast<float2*>(
                    &ctx[((size_t)s * BB + b) * HH + h * HDI + d]) = val;
            }
}

// ---------------------------------------------------------------------------
// Launch
// ---------------------------------------------------------------------------
extern "C" void kernel_launch(void* const* d_in, const int* in_sizes, int n_in,
                              void* d_out, int out_size)
{
    const float* q    = (const float*)d_in[0];
    const float* k    = (const float*)d_in[1];
    const float* v    = (const float*)d_in[2];
    const void*  mask = d_in[3];
    const float* Wq   = (const float*)d_in[4];
    const float* bq   = (const float*)d_in[5];
    const float* Wk   = (const float*)d_in[6];
    const float* bk   = (const float*)d_in[7];
    const float* Wv   = (const float*)d_in[8];
    const float* bv   = (const float*)d_in[9];

    float* out  = (float*)d_out;
    float* ctx  = out;                               // [S,B,H]
    float* attn = out + (size_t)SQ * BB * HH;        // [B,NH,S,S]

    k_detect<<<1, 1>>>((const unsigned*)mask);
    k_bias<<<(BB * SQ + 255) / 256, 256>>>(mask);

    k_proj<<<dim3(HH / 128, (BB * SQ) / 128, 3), 256>>>(
        q, k, v, Wq, bq, Wk, bk, Wv, bv);

    cudaFuncSetAttribute(k_attn, cudaFuncAttributeMaxDynamicSharedMemorySize,
                         F_SMEM_BYTES);
    k_attn<<<dim3(SQ / 128, BB * NHD), 256, F_SMEM_BYTES>>>(attn, ctx);
}

// round 13
// speedup vs baseline: 1.0928x; 1.0928x over previous
#include <cuda_runtime.h>
#include <cuda_bf16.h>

// Problem constants
#define SQ   1024   // sequence length
#define BB   8      // batch
#define HH   1024   // hidden
#define NHD  16     // num heads
#define HDI  64     // head dim

// ---------------------------------------------------------------------------
// Scratch (device globals: no allocation allowed)
// ---------------------------------------------------------------------------
__device__ float g_qp[(size_t)BB * NHD * SQ * HDI];   // [b][h][s][d]
__device__ float g_kp[(size_t)BB * NHD * SQ * HDI];
__device__ float g_vp[(size_t)BB * NHD * SQ * HDI];
__device__ float g_bias[BB * SQ];                     // -1e6 * mask
__device__ int   g_mmode;

// ---------------------------------------------------------------------------
// TF32 helpers
// ---------------------------------------------------------------------------
__device__ __forceinline__ unsigned f2tf(float x) {
    unsigned u;
    asm("cvt.rna.tf32.f32 %0, %1;" : "=r"(u) : "f"(x));
    return u;
}
__device__ __forceinline__ uint4 f2tf4(float4 v) {
    return make_uint4(f2tf(v.x), f2tf(v.y), f2tf(v.z), f2tf(v.w));
}
__device__ __forceinline__ void mma8(float c[4], const unsigned a[4], const unsigned b[2]) {
    asm volatile(
        "mma.sync.aligned.m16n8k8.row.col.f32.tf32.tf32.f32 "
        "{%0,%1,%2,%3}, {%4,%5,%6,%7}, {%8,%9}, {%0,%1,%2,%3};"
        : "+f"(c[0]), "+f"(c[1]), "+f"(c[2]), "+f"(c[3])
        : "r"(a[0]), "r"(a[1]), "r"(a[2]), "r"(a[3]),
          "r"(b[0]), "r"(b[1]));
}

// ---------------------------------------------------------------------------
// Mask dtype detection + bias build
// ---------------------------------------------------------------------------
__global__ void k_detect(const unsigned* __restrict__ m) {
    bool i32 = true, f32 = true;
    for (int i = 0; i < 2048; i++) {
        unsigned v = m[i];
        if (v > 1u) i32 = false;
        if (v != 0u && v != 0x3F800000u) f32 = false;
    }
    g_mmode = i32 ? 1 : (f32 ? 2 : 0);
}
__global__ void k_bias(const void* __restrict__ mask) {
    int i = blockIdx.x * blockDim.x + threadIdx.x;
    if (i >= BB * SQ) return;
    int mode = g_mmode;
    float v;
    if (mode == 1)      v = (float)((const int*)mask)[i];
    else if (mode == 2) v = ((const float*)mask)[i];
    else                v = (float)((const unsigned char*)mask)[i];
    g_bias[i] = v * -1000000.0f;
}

// ---------------------------------------------------------------------------
// Projection GEMM (known-good R10 version, all 3 in one launch):
//   Out[b][h][s][d] = X[m=s*B+b] . W[n] + bias[n]
// BM=128, BN=128, BK=32, 256 thr = 8 warps (2 x 4), warp tile 64x32.
// ---------------------------------------------------------------------------
__global__ __launch_bounds__(256) void k_proj(
    const float* __restrict__ Xq, const float* __restrict__ Xk, const float* __restrict__ Xv,
    const float* __restrict__ Wq, const float* __restrict__ bq,
    const float* __restrict__ Wk, const float* __restrict__ bk,
    const float* __restrict__ Wv, const float* __restrict__ bv)
{
    const int which = blockIdx.z;
    const float* X    = (which == 0) ? Xq : ((which == 1) ? Xk : Xv);
    const float* W    = (which == 0) ? Wq : ((which == 1) ? Wk : Wv);
    const float* bias = (which == 0) ? bq : ((which == 1) ? bk : bv);
    float* Out        = (which == 0) ? g_qp : ((which == 1) ? g_kp : g_vp);

    __shared__ unsigned As[128][36];
    __shared__ unsigned Bs[128][36];

    const int tid  = threadIdx.x;
    const int lane = tid & 31;
    const int warp = tid >> 5;
    const int wm   = warp >> 2;     // 0..1
    const int wn   = warp & 3;      // 0..3
    const int g    = lane >> 2;
    const int t4   = lane & 3;
    const int bm   = blockIdx.y * 128;
    const int bn   = blockIdx.x * 128;

    float acc[4][4][4];
#pragma unroll
    for (int mt = 0; mt < 4; mt++)
#pragma unroll
        for (int nt = 0; nt < 4; nt++)
#pragma unroll
            for (int i = 0; i < 4; i++) acc[mt][nt][i] = 0.0f;

    for (int k0 = 0; k0 < HH; k0 += 32) {
#pragma unroll
        for (int t = 0; t < 4; t++) {
            int i4 = tid + t * 256;
            int r  = i4 >> 3;
            int c  = (i4 & 7) << 2;
            float4 a4 = *reinterpret_cast<const float4*>(&X[(size_t)(bm + r) * HH + k0 + c]);
            *reinterpret_cast<uint4*>(&As[r][c]) = f2tf4(a4);
            float4 b4 = *reinterpret_cast<const float4*>(&W[(size_t)(bn + r) * HH + k0 + c]);
            *reinterpret_cast<uint4*>(&Bs[r][c]) = f2tf4(b4);
        }
        __syncthreads();

#pragma unroll
        for (int k8 = 0; k8 < 4; k8++) {
            const int kk = k8 * 8;
            unsigned a[4][4], bf[4][2];
#pragma unroll
            for (int mt = 0; mt < 4; mt++) {
                const int r = wm * 64 + mt * 16;
                a[mt][0] = As[r + g][kk + t4];
                a[mt][1] = As[r + g + 8][kk + t4];
                a[mt][2] = As[r + g][kk + t4 + 4];
                a[mt][3] = As[r + g + 8][kk + t4 + 4];
            }
#pragma unroll
            for (int nt = 0; nt < 4; nt++) {
                const int n = wn * 32 + nt * 8 + g;
                bf[nt][0] = Bs[n][kk + t4];
                bf[nt][1] = Bs[n][kk + t4 + 4];
            }
#pragma unroll
            for (int mt = 0; mt < 4; mt++)
#pragma unroll
                for (int nt = 0; nt < 4; nt++)
                    mma8(acc[mt][nt], a[mt], bf[nt]);
        }
        __syncthreads();
    }

#pragma unroll
    for (int mt = 0; mt < 4; mt++) {
        const int r0 = bm + wm * 64 + mt * 16 + g;
#pragma unroll
        for (int nt = 0; nt < 4; nt++) {
            const int n0  = bn + wn * 32 + nt * 8 + t4 * 2;
            const float b0v = bias[n0];
            const float b1v = bias[n0 + 1];
            const int h = n0 >> 6;
            const int d = n0 & 63;
#pragma unroll
            for (int half = 0; half < 2; half++) {
                const int m  = r0 + half * 8;
                const int s  = m >> 3;     // m = s*B + b
                const int bb = m & 7;
                float2 val = make_float2(acc[mt][nt][half * 2 + 0] + b0v,
                                         acc[mt][nt][half * 2 + 1] + b1v);
                *reinterpret_cast<float2*>(
                    &Out[(((size_t)bb * NHD + h) * SQ + s) * HDI + d]) = val;
            }
        }
    }
}

// ---------------------------------------------------------------------------
// Fused two-pass flash attention (R10 layout) + smem double-buffering:
//  Pass 1: K tiles ping-pong between Ks and Vs (idle in pass 1) -> one sync
//          per k-tile, K(kt+1) LDGs overlap MMAs on K(kt).
//  Pass 2: after the Ps-ready barrier Ks is dead -> prefetch K(kt+1) into Ks
//          concurrently with the P.V MMA phase.
// smem ~111KB -> 2 blocks/SM.
// ---------------------------------------------------------------------------
#define F_QS   (128 * 68)
#define F_KS   (64 * 68)
#define F_VS   (64 * 72)
#define F_PS   (128 * 68)
#define F_BIAS 1024
#define F_SMEM_FLOATS (F_QS + F_KS + F_VS + F_PS + F_BIAS + 256 + 128)
#define F_SMEM_BYTES  (F_SMEM_FLOATS * 4)

__global__ __launch_bounds__(256, 2) void k_attn(float* __restrict__ attn,
                                                 float* __restrict__ ctx)
{
    extern __shared__ float sm[];
    unsigned* Qs    = (unsigned*)sm;
    unsigned* Ks    = Qs + F_QS;
    unsigned* Vs    = Ks + F_KS;
    unsigned* Ps    = Vs + F_VS;
    float*    sBias = (float*)(Ps + F_PS);
    float*    sSum  = sBias + F_BIAS;
    float*    sInv  = sSum + 256;

    const int tid  = threadIdx.x;
    const int lane = tid & 31;
    const int warp = tid >> 5;
    const int g    = lane >> 2;
    const int t4   = lane & 3;
    const int wm   = warp >> 1;    // 0..3
    const int wn   = warp & 1;     // 0..1
    const int qb   = blockIdx.x;
    const int bh   = blockIdx.y;
    const int b    = bh >> 4;
    const int h    = bh & 15;
    const int fr   = tid >> 4;          // fill row (64-row tiles)
    const int fc   = (tid & 15) << 2;   // fill col

    const float* Qg = g_qp + ((size_t)bh * SQ + qb * 128) * HDI;
    const float* Kg = g_kp + (size_t)bh * SQ * HDI;
    const float* Vg = g_vp + (size_t)bh * SQ * HDI;

    // Load Q tile (128x64, tf32) and bias row (1024)
#pragma unroll
    for (int t = 0; t < 8; t++) {
        int i4 = tid + t * 256;
        int r  = i4 >> 4;
        int c  = (i4 & 15) << 2;
        float4 q4 = *reinterpret_cast<const float4*>(&Qg[r * 64 + c]);
        *reinterpret_cast<uint4*>(&Qs[r * 68 + c]) = f2tf4(q4);
    }
#pragma unroll
    for (int t = 0; t < 4; t++) sBias[tid + t * 256] = g_bias[b * SQ + tid + t * 256];

    // Preload K tile 0 into Ks (buffer 0); Vs serves as buffer 1 in pass 1.
#pragma unroll
    for (int t = 0; t < 4; t++) {
        int r = fr + t * 16;
        float4 k4 = *reinterpret_cast<const float4*>(&Kg[(size_t)r * 64 + fc]);
        *reinterpret_cast<uint4*>(&Ks[r * 68 + fc]) = f2tf4(k4);
    }

    // ======================= Pass 1: row sums ============================
    float rs[2][2] = {};
    for (int kt = 0; kt < 16; kt++) {
        __syncthreads();   // current buffer's writes visible; prior reads done
        unsigned* Kcur  = (kt & 1) ? Vs : Ks;
        unsigned* Knext = (kt & 1) ? Ks : Vs;
        // prefetch next K tile into the other buffer (overlaps MMAs below)
        if (kt < 15) {
#pragma unroll
            for (int t = 0; t < 4; t++) {
                int r = fr + t * 16;
                float4 k4 = *reinterpret_cast<const float4*>(
                    &Kg[(size_t)((kt + 1) * 64 + r) * 64 + fc]);
                *reinterpret_cast<uint4*>(&Knext[r * 68 + fc]) = f2tf4(k4);
            }
        }

        float acc[2][4][4] = {};
#pragma unroll
        for (int k8 = 0; k8 < 8; k8++) {
            const int kk = k8 * 8;
            unsigned a[2][4], bf[4][2];
#pragma unroll
            for (int mt = 0; mt < 2; mt++) {
                const int r = wm * 32 + mt * 16;
                a[mt][0] = Qs[(r + g) * 68 + kk + t4];
                a[mt][1] = Qs[(r + g + 8) * 68 + kk + t4];
                a[mt][2] = Qs[(r + g) * 68 + kk + t4 + 4];
                a[mt][3] = Qs[(r + g + 8) * 68 + kk + t4 + 4];
            }
#pragma unroll
            for (int nt = 0; nt < 4; nt++) {
                const int n = wn * 32 + nt * 8 + g;
                bf[nt][0] = Kcur[n * 68 + kk + t4];
                bf[nt][1] = Kcur[n * 68 + kk + t4 + 4];
            }
#pragma unroll
            for (int mt = 0; mt < 2; mt++)
#pragma unroll
                for (int nt = 0; nt < 4; nt++)
                    mma8(acc[mt][nt], a[mt], bf[nt]);
        }
#pragma unroll
        for (int mt = 0; mt < 2; mt++)
#pragma unroll
            for (int half = 0; half < 2; half++)
#pragma unroll
                for (int nt = 0; nt < 4; nt++) {
                    const int cl = kt * 64 + wn * 32 + nt * 8 + t4 * 2;
                    rs[mt][half] += __expf(acc[mt][nt][half * 2 + 0] * 0.125f + sBias[cl])
                                  + __expf(acc[mt][nt][half * 2 + 1] * 0.125f + sBias[cl + 1]);
                }
    }
    // reduce over t4 lanes, combine both wn warps via smem
#pragma unroll
    for (int mt = 0; mt < 2; mt++)
#pragma unroll
        for (int half = 0; half < 2; half++) {
            float v = rs[mt][half];
            v += __shfl_xor_sync(0xffffffffu, v, 1);
            v += __shfl_xor_sync(0xffffffffu, v, 2);
            if (t4 == 0) {
                const int row = wm * 32 + mt * 16 + g + half * 8;
                sSum[row * 2 + wn] = v;
            }
        }
    __syncthreads();
    if (tid < 128) sInv[tid] = 1.0f / (sSum[tid * 2] + sSum[tid * 2 + 1]);

    // Preload K tile 0 into Ks for pass 2 (visible after loop-top sync)
#pragma unroll
    for (int t = 0; t < 4; t++) {
        int r = fr + t * 16;
        float4 k4 = *reinterpret_cast<const float4*>(&Kg[(size_t)r * 64 + fc]);
        *reinterpret_cast<uint4*>(&Ks[r * 68 + fc]) = f2tf4(k4);
    }

    // ======================= Pass 2: attn + O ============================
    float o[2][4][4] = {};
    float* attn_base = attn + ((size_t)bh * SQ + qb * 128) * SQ;

    for (int kt = 0; kt < 16; kt++) {
        __syncthreads();   // prev PV reads done (Vs free); K prefetch visible
        // V tile for this kt (K already resident from prefetch)
#pragma unroll
        for (int t = 0; t < 4; t++) {
            int r = fr + t * 16;
            float4 v4 = *reinterpret_cast<const float4*>(&Vg[(size_t)(kt * 64 + r) * 64 + fc]);
            *reinterpret_cast<uint4*>(&Vs[r * 72 + fc]) = f2tf4(v4);
        }
        __syncthreads();

        float acc[2][4][4] = {};
#pragma unroll
        for (int k8 = 0; k8 < 8; k8++) {
            const int kk = k8 * 8;
            unsigned a[2][4], bf[4][2];
#pragma unroll
            for (int mt = 0; mt < 2; mt++) {
                const int r = wm * 32 + mt * 16;
                a[mt][0] = Qs[(r + g) * 68 + kk + t4];
                a[mt][1] = Qs[(r + g + 8) * 68 + kk + t4];
                a[mt][2] = Qs[(r + g) * 68 + kk + t4 + 4];
                a[mt][3] = Qs[(r + g + 8) * 68 + kk + t4 + 4];
            }
#pragma unroll
            for (int nt = 0; nt < 4; nt++) {
                const int n = wn * 32 + nt * 8 + g;
                bf[nt][0] = Ks[n * 68 + kk + t4];
                bf[nt][1] = Ks[n * 68 + kk + t4 + 4];
            }
#pragma unroll
            for (int mt = 0; mt < 2; mt++)
#pragma unroll
                for (int nt = 0; nt < 4; nt++)
                    mma8(acc[mt][nt], a[mt], bf[nt]);
        }

        // normalized exp -> attn (single write) + Ps (tf32 stage)
#pragma unroll
        for (int mt = 0; mt < 2; mt++)
#pragma unroll
            for (int half = 0; half < 2; half++) {
                const int row = wm * 32 + mt * 16 + g + half * 8;
                const float inv = sInv[row];
#pragma unroll
                for (int nt = 0; nt < 4; nt++) {
                    const int cl = wn * 32 + nt * 8 + t4 * 2;
                    const int key = kt * 64 + cl;
                    float p0 = __expf(acc[mt][nt][half * 2 + 0] * 0.125f + sBias[key]) * inv;
                    float p1 = __expf(acc[mt][nt][half * 2 + 1] * 0.125f + sBias[key + 1]) * inv;
                    *reinterpret_cast<float2*>(&attn_base[(size_t)row * SQ + key]) =
                        make_float2(p0, p1);
                    Ps[row * 68 + cl]     = f2tf(p0);
                    Ps[row * 68 + cl + 1] = f2tf(p1);
                }
            }
        __syncthreads();   // Ps complete; all QK reads of Ks done -> Ks free

        // prefetch next K tile into Ks (overlaps the PV MMAs below)
        if (kt < 15) {
#pragma unroll
            for (int t = 0; t < 4; t++) {
                int r = fr + t * 16;
                float4 k4 = *reinterpret_cast<const float4*>(
                    &Kg[(size_t)((kt + 1) * 64 + r) * 64 + fc]);
                *reinterpret_cast<uint4*>(&Ks[r * 68 + fc]) = f2tf4(k4);
            }
        }

        // O += P . V
#pragma unroll
        for (int k8 = 0; k8 < 8; k8++) {
            const int kk = k8 * 8;
            unsigned a[2][4], bf[4][2];
#pragma unroll
            for (int mt = 0; mt < 2; mt++) {
                const int r = wm * 32 + mt * 16;
                a[mt][0] = Ps[(r + g) * 68 + kk + t4];
                a[mt][1] = Ps[(r + g + 8) * 68 + kk + t4];
                a[mt][2] = Ps[(r + g) * 68 + kk + t4 + 4];
                a[mt][3] = Ps[(r + g + 8) * 68 + kk + t4 + 4];
            }
#pragma unroll
            for (int nt = 0; nt < 4; nt++) {
                const int n = wn * 32 + nt * 8 + g;   // head-dim column
                bf[nt][0] = Vs[(kk + t4) * 72 + n];
                bf[nt][1] = Vs[(kk + t4 + 4) * 72 + n];
            }
#pragma unroll
            for (int mt = 0; mt < 2; mt++)
#pragma unroll
                for (int nt = 0; nt < 4; nt++)
                    mma8(o[mt][nt], a[mt], bf[nt]);
        }
    }

    // Epilogue: ctx[s][b][h*64+d]  (already normalized)
#pragma unroll
    for (int mt = 0; mt < 2; mt++)
#pragma unroll
        for (int nt = 0; nt < 4; nt++)
#pragma unroll
            for (int half = 0; half < 2; half++) {
                int row = wm * 32 + mt * 16 + g + half * 8;
                int s   = qb * 128 + row;
                int d   = wn * 32 + nt * 8 + t4 * 2;
                float2 val = make_float2(o[mt][nt][half * 2 + 0],
                                         o[mt][nt][half * 2 + 1]);
                *reinterpret_cast<float2*>(
                    &ctx[((size_t)s * BB + b) * HH + h * HDI + d]) = val;
            }
}

// ---------------------------------------------------------------------------
// Launch
// ---------------------------------------------------------------------------
extern "C" void kernel_launch(void* const* d_in, const int* in_sizes, int n_in,
                              void* d_out, int out_size)
{
    const float* q    = (const float*)d_in[0];
    const float* k    = (const float*)d_in[1];
    const float* v    = (const float*)d_in[2];
    const void*  mask = d_in[3];
    const float* Wq   = (const float*)d_in[4];
    const float* bq   = (const float*)d_in[5];
    const float* Wk   = (const float*)d_in[6];
    const float* bk   = (const float*)d_in[7];
    const float* Wv   = (const float*)d_in[8];
    const float* bv   = (const float*)d_in[9];

    float* out  = (float*)d_out;
    float* ctx  = out;                               // [S,B,H]
    float* attn = out + (size_t)SQ * BB * HH;        // [B,NH,S,S]

    k_detect<<<1, 1>>>((const unsigned*)mask);
    k_bias<<<(BB * SQ + 255) / 256, 256>>>(mask);

    k_proj<<<dim3(HH / 128, (BB * SQ) / 128, 3), 256>>>(
        q, k, v, Wq, bq, Wk, bk, Wv, bv);

    cudaFuncSetAttribute(k_attn, cudaFuncAttributeMaxDynamicSharedMemorySize,
                         F_SMEM_BYTES);
    k_attn<<<dim3(SQ / 128, BB * NHD), 256, F_SMEM_BYTES>>>(attn, ctx);
}